// round 16
// baseline (speedup 1.0000x reference)
#include <cuda_runtime.h>

#define NN   5000
#define SB   49
#define SBR  19
#define YR   2
#define CC   128
#define HH   256
#define NBF  512
#define EE   10000
#define EY   (EE*YR)          // 20000
#define SBRC (SBR*CC)         // 2432
#define MSGIN (2*SBRC)        // 4864

// -------- scratch (device globals; no allocation allowed) --------
__device__ float g_gate [(size_t)EE * HH];      // silu(x_edge@w_dist+b)      ~10 MB
__device__ float g_msgin[(size_t)EY * MSGIN];   // rotated+concat messages    ~389 MB
__device__ float g_h1   [(size_t)EY * HH];      // silu(proj)*gate            ~20 MB
__device__ float g_h2   [(size_t)EY * HH];      // silu(edge)                 ~20 MB
__device__ float g_h3   [(size_t)EY * SBRC];    // silu(out)                  ~195 MB

__device__ __forceinline__ float silu_f(float v) {
    return v / (1.0f + __expf(-v));
}

// ============================================================================
// Generic SGEMM:  Cm[M,N] = silu(A[M,K] @ B[K,N] + bias[N])  (* gate[row>>1,:])
// 128x128 tile, BK=8, 256 threads, 8x8 per-thread register tile.
// Requires: N % 128 == 0, K % 8 == 0, pointers 16B aligned. M guarded.
// ============================================================================
template<int GATE>
__global__ __launch_bounds__(256)
void sgemm_fused(const float* __restrict__ A, const float* __restrict__ B,
                 const float* __restrict__ bias, const float* __restrict__ gate,
                 float* __restrict__ Cm, int M, int Nn, int K)
{
    __shared__ float As[8][128];   // transposed A tile
    __shared__ float Bs[8][128];

    const int tid   = threadIdx.x;
    const int mTile = blockIdx.y * 128;
    const int nTile = blockIdx.x * 128;

    const int aRow = tid >> 1;            // 0..127
    const int aCol = (tid & 1) * 4;       // 0 or 4
    const int bRow = tid >> 5;            // 0..7
    const int bCol = (tid & 31) * 4;      // 0..124
    const int ty   = tid >> 4;            // 0..15
    const int tx   = tid & 15;            // 0..15

    const bool aValid = (mTile + aRow) < M;
    const float* Aptr = A + (size_t)(mTile + aRow) * K + aCol;
    const float* Bp   = B + (size_t)bRow * Nn + nTile + bCol;

    float acc[8][8] = {};

    for (int k0 = 0; k0 < K; k0 += 8) {
        float4 av = aValid ? *(const float4*)(Aptr + k0)
                           : make_float4(0.f, 0.f, 0.f, 0.f);
        As[aCol+0][aRow] = av.x;
        As[aCol+1][aRow] = av.y;
        As[aCol+2][aRow] = av.z;
        As[aCol+3][aRow] = av.w;
        float4 bv = *(const float4*)(Bp + (size_t)k0 * Nn);
        *(float4*)&Bs[bRow][bCol] = bv;
        __syncthreads();

#pragma unroll
        for (int kk = 0; kk < 8; kk++) {
            float ar[8], br[8];
#pragma unroll
            for (int i = 0; i < 8; i++) ar[i] = As[kk][ty*8 + i];
#pragma unroll
            for (int j = 0; j < 8; j++) br[j] = Bs[kk][tx*8 + j];
#pragma unroll
            for (int i = 0; i < 8; i++)
#pragma unroll
                for (int j = 0; j < 8; j++)
                    acc[i][j] += ar[i] * br[j];
        }
        __syncthreads();
    }

#pragma unroll
    for (int i = 0; i < 8; i++) {
        int r = mTile + ty*8 + i;
        if (r >= M) break;
        const float* grow = GATE ? (gate + (size_t)(r >> 1) * Nn) : (const float*)0;
#pragma unroll
        for (int j = 0; j < 8; j += 4) {
            int col = nTile + tx*8 + j;
            float4 o;
            o.x = silu_f(acc[i][j+0] + bias[col+0]);
            o.y = silu_f(acc[i][j+1] + bias[col+1]);
            o.z = silu_f(acc[i][j+2] + bias[col+2]);
            o.w = silu_f(acc[i][j+3] + bias[col+3]);
            if (GATE) {
                float4 g = *(const float4*)&grow[col];
                o.x *= g.x; o.y *= g.y; o.z *= g.z; o.w *= g.w;
            }
            *(float4*)&Cm[(size_t)r * Nn + col] = o;
        }
    }
}

// ============================================================================
// rotate: block = (edge e, which in {source,target}); 128 threads (one per C).
// Stages x[node] (49x128) and BOTH per-y Wigner matrices (transposed) in smem;
// each thread accumulates 2x19 outputs -> msgin rows (e*2+y), col block `which`.
// ============================================================================
__global__ __launch_bounds__(128)
void rotate_kernel(const float* __restrict__ x, const int* __restrict__ edge_index,
                   const float* __restrict__ wigner, float* __restrict__ msgin)
{
    __shared__ float Xs[SB * CC];        // 25 KB
    __shared__ float Wt[YR][SB][20];     // transposed + padded, 7.8 KB

    const int e     = blockIdx.x;
    const int which = blockIdx.y;        // 0 = source row, 1 = target row
    const int tid   = threadIdx.x;

    const int node = edge_index[which * EE + e];
    const float4* xp = (const float4*)(x + (size_t)node * SB * CC);
    float4* Xs4 = (float4*)Xs;
    for (int i = tid; i < SB*CC/4; i += 128) Xs4[i] = xp[i];

    const float* w0p = wigner + (size_t)(e * YR) * SBR * SB;
    for (int i = tid; i < SBR*SB; i += 128) {
        int s = i / SB, b = i - s*SB;
        Wt[0][b][s] = w0p[i];
        Wt[1][b][s] = w0p[SBR*SB + i];
    }
    __syncthreads();

    float acc0[SBR], acc1[SBR];
#pragma unroll
    for (int s = 0; s < SBR; s++) { acc0[s] = 0.f; acc1[s] = 0.f; }

    const int c = tid;
    for (int b = 0; b < SB; b++) {
        float xv = Xs[b*CC + c];
        const float* w0 = Wt[0][b];
        const float* w1 = Wt[1][b];
#pragma unroll
        for (int s = 0; s < SBR; s++) {
            acc0[s] += w0[s] * xv;
            acc1[s] += w1[s] * xv;
        }
    }

    float* o0 = msgin + (size_t)(e * YR) * MSGIN + which * SBRC + c;
    float* o1 = o0 + MSGIN;
#pragma unroll
    for (int s = 0; s < SBR; s++) {
        o0[s*CC] = acc0[s];
        o1[s*CC] = acc1[s];
    }
}

// ============================================================================
// invrot: block = edge; fuse mean over Y with wigner_inv product.
// out[e,b,c] = sum_s winv[e,b,s] * 0.5*(h3[e*2,s,c] + h3[e*2+1,s,c])
// ============================================================================
__global__ __launch_bounds__(128)
void invrot_kernel(const float* __restrict__ h3, const float* __restrict__ winv,
                   float* __restrict__ out)
{
    __shared__ float Ms[SBR * CC];   // 9.7 KB
    __shared__ float Wt[SBR][52];    // transposed winv, padded

    const int e   = blockIdx.x;
    const int tid = threadIdx.x;

    const float* r0 = h3 + (size_t)(e * YR) * SBRC;
    for (int i = tid; i < SBRC; i += 128)
        Ms[i] = 0.5f * (r0[i] + r0[SBRC + i]);

    const float* wv = winv + (size_t)e * SB * SBR;   // [49][19]
    for (int i = tid; i < SB*SBR; i += 128) {
        int b = i / SBR, s = i - b*SBR;
        Wt[s][b] = wv[i];
    }
    __syncthreads();

    float acc[SB];
#pragma unroll
    for (int b = 0; b < SB; b++) acc[b] = 0.f;

    const int c = tid;
    for (int s = 0; s < SBR; s++) {
        float mv = Ms[s*CC + c];
        const float* w = Wt[s];
#pragma unroll
        for (int b = 0; b < SB; b++) acc[b] += w[b] * mv;
    }

    float* o = out + (size_t)e * SB * CC + c;
#pragma unroll
    for (int b = 0; b < SB; b++) o[b*CC] = acc[b];
}

// ============================================================================
extern "C" void kernel_launch(void* const* d_in, const int* in_sizes, int n_in,
                              void* d_out, int out_size)
{
    const float* x      = (const float*)d_in[0];   // [N,49,128]
    const float* x_edge = (const float*)d_in[1];   // [E,512]
    const int*   eidx   = (const int*)  d_in[2];   // [2,E] int32
    const float* wigner = (const float*)d_in[3];   // [E*2,19,49]
    const float* winv   = (const float*)d_in[4];   // [E,49,19]
    const float* w_dist = (const float*)d_in[5];   // [512,256]
    const float* b_dist = (const float*)d_in[6];   // [256]
    const float* w_proj = (const float*)d_in[7];   // [4864,256]
    const float* b_proj = (const float*)d_in[8];   // [256]
    const float* w_edge = (const float*)d_in[9];   // [256,256]
    const float* b_edge = (const float*)d_in[10];  // [256]
    const float* w_out  = (const float*)d_in[11];  // [256,2432]
    const float* b_out  = (const float*)d_in[12];  // [2432]
    float* out = (float*)d_out;                    // [E,49,128]

    float *p_gate, *p_msgin, *p_h1, *p_h2, *p_h3;
    cudaGetSymbolAddress((void**)&p_gate,  g_gate);
    cudaGetSymbolAddress((void**)&p_msgin, g_msgin);
    cudaGetSymbolAddress((void**)&p_h1,    g_h1);
    cudaGetSymbolAddress((void**)&p_h2,    g_h2);
    cudaGetSymbolAddress((void**)&p_h3,    g_h3);

    // 1. distance gate: [E,512]@[512,256] + bias, silu
    sgemm_fused<0><<<dim3(HH/128, (EE + 127)/128), 256>>>(
        x_edge, w_dist, b_dist, nullptr, p_gate, EE, HH, NBF);

    // 2. rotate + concat -> g_msgin [EY, 4864]
    rotate_kernel<<<dim3(EE, 2), 128>>>(x, eidx, wigner, p_msgin);

    // 3. proj: [EY,4864]@[4864,256] + bias, silu, * gate (fused)
    sgemm_fused<1><<<dim3(HH/128, (EY + 127)/128), 256>>>(
        p_msgin, w_proj, b_proj, p_gate, p_h1, EY, HH, MSGIN);

    // 4. edge: [EY,256]@[256,256] + bias, silu
    sgemm_fused<0><<<dim3(HH/128, (EY + 127)/128), 256>>>(
        p_h1, w_edge, b_edge, nullptr, p_h2, EY, HH, HH);

    // 5. out: [EY,256]@[256,2432] + bias, silu
    sgemm_fused<0><<<dim3(SBRC/128, (EY + 127)/128), 256>>>(
        p_h2, w_out, b_out, nullptr, p_h3, EY, SBRC, HH);

    // 6. mean over Y + inverse rotation -> d_out
    invrot_kernel<<<EE, 128>>>(p_h3, winv, out);
}

// round 17
// speedup vs baseline: 1.2001x; 1.2001x over previous
#include <cuda_runtime.h>
#include <cstdint>

#define NN   5000
#define SB   49
#define SBR  19
#define YR   2
#define CC   128
#define HH   256
#define NBF  512
#define EE   10000
#define EY   (EE*YR)          // 20000
#define SBRC (SBR*CC)         // 2432
#define MSGIN (2*SBRC)        // 4864

// -------- scratch (device globals; no allocation allowed) --------
__device__ float g_gate [(size_t)EE * HH];
__device__ float g_msgin[(size_t)EY * MSGIN];
__device__ float g_h1   [(size_t)EY * HH];
__device__ float g_h2   [(size_t)EY * HH];
__device__ float g_h3   [(size_t)EY * SBRC];

__device__ __forceinline__ float silu_f(float v) {
    return v / (1.0f + __expf(-v));
}

// split fp32 -> hi/lo tf32 pair (3xTF32 trick)
__device__ __forceinline__ void split_tf32(float x, uint32_t& hi, uint32_t& lo) {
    asm("cvt.rna.tf32.f32 %0, %1;" : "=r"(hi) : "f"(x));
    float l = x - __uint_as_float(hi);
    asm("cvt.rna.tf32.f32 %0, %1;" : "=r"(lo) : "f"(l));
}

__device__ __forceinline__ void mma_tf32(float4& c, const uint32_t a[4], const uint32_t b[2]) {
    asm("mma.sync.aligned.m16n8k8.row.col.f32.tf32.tf32.f32 "
        "{%0,%1,%2,%3},{%4,%5,%6,%7},{%8,%9},{%0,%1,%2,%3};"
        : "+f"(c.x), "+f"(c.y), "+f"(c.z), "+f"(c.w)
        : "r"(a[0]), "r"(a[1]), "r"(a[2]), "r"(a[3]), "r"(b[0]), "r"(b[1]));
}

// ============================================================================
// Tensor-core GEMM (3xTF32): Cm[M,N] = silu(A@B + bias) (* gate[row>>1,:])
// 128x128 tile, BK=16, 256 threads, 8 warps (2x4), warp tile 64x32.
// Requires N % 128 == 0, K % 16 == 0. M guarded.
// ============================================================================
template<int GATE>
__global__ __launch_bounds__(256)
void tgemm_fused(const float* __restrict__ A, const float* __restrict__ B,
                 const float* __restrict__ bias, const float* __restrict__ gate,
                 float* __restrict__ Cm, int M, int Nn, int K)
{
    __shared__ float As[16][132];   // [k][m], padded
    __shared__ float Bs[16][132];   // [k][n], padded

    const int tid  = threadIdx.x;
    const int lane = tid & 31;
    const int warp = tid >> 5;
    const int wr = warp >> 2;          // 0..1  (64-row slab)
    const int wc = warp & 3;           // 0..3  (32-col slab)
    const int lr = lane >> 2;          // 0..7
    const int lc = lane & 3;           // 0..3

    const int mTile = blockIdx.y * 128;
    const int nTile = blockIdx.x * 128;

    // A staging: thread -> row tid>>1, k-half (tid&1)*8 (two float4)
    const int aRow = tid >> 1;
    const int aK   = (tid & 1) * 8;
    const bool aValid = (mTile + aRow) < M;
    const float* Ap = A + (size_t)(mTile + aRow) * K + aK;

    // B staging: rows tid>>5 and +8, 4 floats at (tid&31)*4
    const int bR = tid >> 5;
    const int bC = (tid & 31) * 4;
    const float* Bp = B + (size_t)bR * Nn + nTile + bC;

    float4 acc[4][4];
#pragma unroll
    for (int i = 0; i < 4; i++)
#pragma unroll
        for (int j = 0; j < 4; j++) acc[i][j] = make_float4(0.f, 0.f, 0.f, 0.f);

    for (int k0 = 0; k0 < K; k0 += 16) {
        float4 av0, av1;
        if (aValid) {
            av0 = *(const float4*)(Ap + k0);
            av1 = *(const float4*)(Ap + k0 + 4);
        } else {
            av0 = av1 = make_float4(0.f, 0.f, 0.f, 0.f);
        }
        As[aK+0][aRow] = av0.x; As[aK+1][aRow] = av0.y;
        As[aK+2][aRow] = av0.z; As[aK+3][aRow] = av0.w;
        As[aK+4][aRow] = av1.x; As[aK+5][aRow] = av1.y;
        As[aK+6][aRow] = av1.z; As[aK+7][aRow] = av1.w;

        *(float4*)&Bs[bR  ][bC] = *(const float4*)(Bp + (size_t)k0 * Nn);
        *(float4*)&Bs[bR+8][bC] = *(const float4*)(Bp + (size_t)(k0+8) * Nn);
        __syncthreads();

#pragma unroll
        for (int ks = 0; ks < 16; ks += 8) {
            uint32_t ah[4][4], al[4][4], bh[4][2], bl[4][2];
#pragma unroll
            for (int i = 0; i < 4; i++) {
                int m = wr*64 + i*16 + lr;
                split_tf32(As[ks+lc  ][m  ], ah[i][0], al[i][0]);
                split_tf32(As[ks+lc  ][m+8], ah[i][1], al[i][1]);
                split_tf32(As[ks+lc+4][m  ], ah[i][2], al[i][2]);
                split_tf32(As[ks+lc+4][m+8], ah[i][3], al[i][3]);
            }
#pragma unroll
            for (int j = 0; j < 4; j++) {
                int n = wc*32 + j*8 + lr;
                split_tf32(Bs[ks+lc  ][n], bh[j][0], bl[j][0]);
                split_tf32(Bs[ks+lc+4][n], bh[j][1], bl[j][1]);
            }
#pragma unroll
            for (int i = 0; i < 4; i++)
#pragma unroll
                for (int j = 0; j < 4; j++) {
                    mma_tf32(acc[i][j], al[i], bh[j]);   // lo*hi
                    mma_tf32(acc[i][j], ah[i], bl[j]);   // hi*lo
                    mma_tf32(acc[i][j], ah[i], bh[j]);   // hi*hi
                }
        }
        __syncthreads();
    }

    // epilogue: c0:(r,c) c1:(r,c+1) c2:(r+8,c) c3:(r+8,c+1)
#pragma unroll
    for (int i = 0; i < 4; i++) {
        int row0 = mTile + wr*64 + i*16 + lr;
        int row1 = row0 + 8;
#pragma unroll
        for (int j = 0; j < 4; j++) {
            int col = nTile + wc*32 + j*8 + 2*lc;
            float4 v = acc[i][j];
            float b0 = bias[col], b1 = bias[col+1];
            if (row0 < M) {
                float2 o;
                o.x = silu_f(v.x + b0);
                o.y = silu_f(v.y + b1);
                if (GATE) {
                    const float* g = gate + (size_t)(row0 >> 1) * Nn + col;
                    o.x *= g[0]; o.y *= g[1];
                }
                *(float2*)&Cm[(size_t)row0 * Nn + col] = o;
            }
            if (row1 < M) {
                float2 o;
                o.x = silu_f(v.z + b0);
                o.y = silu_f(v.w + b1);
                if (GATE) {
                    const float* g = gate + (size_t)(row1 >> 1) * Nn + col;
                    o.x *= g[0]; o.y *= g[1];
                }
                *(float2*)&Cm[(size_t)row1 * Nn + col] = o;
            }
        }
    }
}

// ============================================================================
// rotate: block = (edge e, src/tgt); 128 threads (one per C).
// ============================================================================
__global__ __launch_bounds__(128)
void rotate_kernel(const float* __restrict__ x, const int* __restrict__ edge_index,
                   const float* __restrict__ wigner, float* __restrict__ msgin)
{
    __shared__ float Xs[SB * CC];
    __shared__ float Wt[YR][SB][20];

    const int e     = blockIdx.x;
    const int which = blockIdx.y;
    const int tid   = threadIdx.x;

    const int node = edge_index[which * EE + e];
    const float4* xp = (const float4*)(x + (size_t)node * SB * CC);
    float4* Xs4 = (float4*)Xs;
    for (int i = tid; i < SB*CC/4; i += 128) Xs4[i] = xp[i];

    const float* w0p = wigner + (size_t)(e * YR) * SBR * SB;
    for (int i = tid; i < SBR*SB; i += 128) {
        int s = i / SB, b = i - s*SB;
        Wt[0][b][s] = w0p[i];
        Wt[1][b][s] = w0p[SBR*SB + i];
    }
    __syncthreads();

    float acc0[SBR], acc1[SBR];
#pragma unroll
    for (int s = 0; s < SBR; s++) { acc0[s] = 0.f; acc1[s] = 0.f; }

    const int c = tid;
    for (int b = 0; b < SB; b++) {
        float xv = Xs[b*CC + c];
        const float* w0 = Wt[0][b];
        const float* w1 = Wt[1][b];
#pragma unroll
        for (int s = 0; s < SBR; s++) {
            acc0[s] += w0[s] * xv;
            acc1[s] += w1[s] * xv;
        }
    }

    float* o0 = msgin + (size_t)(e * YR) * MSGIN + which * SBRC + c;
    float* o1 = o0 + MSGIN;
#pragma unroll
    for (int s = 0; s < SBR; s++) {
        o0[s*CC] = acc0[s];
        o1[s*CC] = acc1[s];
    }
}

// ============================================================================
// invrot: block = edge; fuse mean over Y with wigner_inv product.
// ============================================================================
__global__ __launch_bounds__(128)
void invrot_kernel(const float* __restrict__ h3, const float* __restrict__ winv,
                   float* __restrict__ out)
{
    __shared__ float Ms[SBR * CC];
    __shared__ float Wt[SBR][52];

    const int e   = blockIdx.x;
    const int tid = threadIdx.x;

    const float* r0 = h3 + (size_t)(e * YR) * SBRC;
    for (int i = tid; i < SBRC; i += 128)
        Ms[i] = 0.5f * (r0[i] + r0[SBRC + i]);

    const float* wv = winv + (size_t)e * SB * SBR;
    for (int i = tid; i < SB*SBR; i += 128) {
        int b = i / SBR, s = i - b*SBR;
        Wt[s][b] = wv[i];
    }
    __syncthreads();

    float acc[SB];
#pragma unroll
    for (int b = 0; b < SB; b++) acc[b] = 0.f;

    const int c = tid;
    for (int s = 0; s < SBR; s++) {
        float mv = Ms[s*CC + c];
        const float* w = Wt[s];
#pragma unroll
        for (int b = 0; b < SB; b++) acc[b] += w[b] * mv;
    }

    float* o = out + (size_t)e * SB * CC + c;
#pragma unroll
    for (int b = 0; b < SB; b++) o[b*CC] = acc[b];
}

// ============================================================================
extern "C" void kernel_launch(void* const* d_in, const int* in_sizes, int n_in,
                              void* d_out, int out_size)
{
    const float* x      = (const float*)d_in[0];
    const float* x_edge = (const float*)d_in[1];
    const int*   eidx   = (const int*)  d_in[2];
    const float* wigner = (const float*)d_in[3];
    const float* winv   = (const float*)d_in[4];
    const float* w_dist = (const float*)d_in[5];
    const float* b_dist = (const float*)d_in[6];
    const float* w_proj = (const float*)d_in[7];
    const float* b_proj = (const float*)d_in[8];
    const float* w_edge = (const float*)d_in[9];
    const float* b_edge = (const float*)d_in[10];
    const float* w_out  = (const float*)d_in[11];
    const float* b_out  = (const float*)d_in[12];
    float* out = (float*)d_out;

    float *p_gate, *p_msgin, *p_h1, *p_h2, *p_h3;
    cudaGetSymbolAddress((void**)&p_gate,  g_gate);
    cudaGetSymbolAddress((void**)&p_msgin, g_msgin);
    cudaGetSymbolAddress((void**)&p_h1,    g_h1);
    cudaGetSymbolAddress((void**)&p_h2,    g_h2);
    cudaGetSymbolAddress((void**)&p_h3,    g_h3);

    // 1. distance gate: [E,512]@[512,256]
    tgemm_fused<0><<<dim3(HH/128, (EE + 127)/128), 256>>>(
        x_edge, w_dist, b_dist, nullptr, p_gate, EE, HH, NBF);

    // 2. rotate + concat -> g_msgin [EY, 4864]
    rotate_kernel<<<dim3(EE, 2), 128>>>(x, eidx, wigner, p_msgin);

    // 3. proj: [EY,4864]@[4864,256], silu, * gate (fused)
    tgemm_fused<1><<<dim3(HH/128, (EY + 127)/128), 256>>>(
        p_msgin, w_proj, b_proj, p_gate, p_h1, EY, HH, MSGIN);

    // 4. edge: [EY,256]@[256,256]
    tgemm_fused<0><<<dim3(HH/128, (EY + 127)/128), 256>>>(
        p_h1, w_edge, b_edge, nullptr, p_h2, EY, HH, HH);

    // 5. out: [EY,256]@[256,2432]
    tgemm_fused<0><<<dim3(SBRC/128, (EY + 127)/128), 256>>>(
        p_h2, w_out, b_out, nullptr, p_h3, EY, SBRC, HH);

    // 6. mean over Y + inverse rotation -> d_out
    invrot_kernel<<<EE, 128>>>(p_h3, winv, out);
}